// round 10
// baseline (speedup 1.0000x reference)
#include <cuda_runtime.h>
#include <cuda_bf16.h>
#include <cstdint>

#define NUM_TYPES 3
#define NQ_MAX 500000
#define BSEG_MAX 4000000
#define MAX_TS 10
#define EPS 1e-7f

// ---------------- device scratch (no allocations allowed) ----------------
__device__ float  g_stats[NUM_TYPES * 3];     // per type: sum, sumsq, cnt
__device__ float2 g_qab[NQ_MAX];              // per question: (A=a_i, B=b_i)
__device__ float2 g_acc[BSEG_MAX];            // per segment: (sum exp(logit), count)
__device__ float  g_exp_ts[MAX_TS + 1];       // exp(team_size_bias)
__device__ int    g_is64;                     // 1 if index arrays are int64

__device__ __forceinline__ int idx_at(const void* p, int i, int is64) {
    return is64 ? (int)((const long long*)p)[i] : ((const int*)p)[i];
}

// ---------------- kernel 0: detect dtype + zero stats + exp(ts_bias) ----------------
__global__ void k_detect(const void* __restrict__ pidx,
                         const float* __restrict__ ts_bias) {
    if (threadIdx.x < NUM_TYPES * 3) g_stats[threadIdx.x] = 0.f;
    if (threadIdx.x < MAX_TS + 1) g_exp_ts[threadIdx.x] = __expf(ts_bias[threadIdx.x]);
    if (threadIdx.x == 0) {
        const int* p32 = (const int*)pidx;
        int any = 0;
        #pragma unroll 8
        for (int k = 0; k < 256; k++) any |= p32[2 * k + 1];
        g_is64 = (any == 0) ? 1 : 0;
    }
}

// ---------------- kernel 1: per-type dl stats ----------------
__global__ void __launch_bounds__(256) k_stats(const float* __restrict__ dl,
                                               const void* __restrict__ type,
                                               int n) {
    const int is64 = g_is64;
    float s[NUM_TYPES]  = {0.f, 0.f, 0.f};
    float s2[NUM_TYPES] = {0.f, 0.f, 0.f};
    float c[NUM_TYPES]  = {0.f, 0.f, 0.f};
    for (int i = blockIdx.x * blockDim.x + threadIdx.x; i < n;
         i += gridDim.x * blockDim.x) {
        int t = idx_at(type, i, is64);
        if (t < 0) t = 0; if (t >= NUM_TYPES) t = NUM_TYPES - 1;
        float v = dl[i];
        s[t]  += v;
        s2[t] += v * v;
        c[t]  += 1.f;
    }
    const unsigned FULL = 0xffffffffu;
    #pragma unroll
    for (int t = 0; t < NUM_TYPES; t++) {
        #pragma unroll
        for (int d = 16; d > 0; d >>= 1) {
            s[t]  += __shfl_down_sync(FULL, s[t], d);
            s2[t] += __shfl_down_sync(FULL, s2[t], d);
            c[t]  += __shfl_down_sync(FULL, c[t], d);
        }
    }
    __shared__ float sh[NUM_TYPES * 3];
    if (threadIdx.x < NUM_TYPES * 3) sh[threadIdx.x] = 0.f;
    __syncthreads();
    if ((threadIdx.x & 31) == 0) {
        #pragma unroll
        for (int t = 0; t < NUM_TYPES; t++) {
            atomicAdd(&sh[t * 3 + 0], s[t]);
            atomicAdd(&sh[t * 3 + 1], s2[t]);
            atomicAdd(&sh[t * 3 + 2], c[t]);
        }
    }
    __syncthreads();
    if (threadIdx.x < NUM_TYPES * 3) atomicAdd(&g_stats[threadIdx.x], sh[threadIdx.x]);
}

// ---------------- kernel 2: per-question A/B precompute + zero g_acc ----------------
__global__ void __launch_bounds__(256) k_question(const float* __restrict__ b,
                                                  const float* __restrict__ log_a,
                                                  const float* __restrict__ dl,
                                                  const void* __restrict__ type,
                                                  const float* __restrict__ dl_scale,
                                                  const float* __restrict__ type_bias,
                                                  int n, int bseg) {
    int i = blockIdx.x * blockDim.x + threadIdx.x;

    // zero 2 float2 accumulator slots (float4 store)
    int j = i * 2;
    if (j + 1 < bseg) {
        *(float4*)&g_acc[j] = make_float4(0.f, 0.f, 0.f, 0.f);
    } else if (j < bseg) {
        g_acc[j] = make_float2(0.f, 0.f);
    }

    if (i >= n) return;
    int t = idx_at(type, i, g_is64);
    if (t < 0) t = 0; if (t >= NUM_TYPES) t = NUM_TYPES - 1;
    float sum  = g_stats[t * 3 + 0];
    float sum2 = g_stats[t * 3 + 1];
    float cnt  = g_stats[t * 3 + 2];
    float sc   = fmaxf(cnt, 1.f);
    float mean = sum / sc;
    float ex2  = sum2 / sc;
    float stdv = sqrtf(fmaxf(ex2 - mean * mean, 0.f));
    mean = (cnt > 0.f) ? mean : 0.f;
    stdv = (cnt > 0.f && stdv > 1e-6f) ? stdv : 1.f;
    float dln = (dl[i] - mean) / stdv;
    float Bv  = b[i] + type_bias[t] + dl_scale[t] * dln;
    float Av  = fmaxf(expf(log_a[i]), EPS);
    g_qab[i]  = make_float2(Av, Bv);
}

// ---------------- kernel 3: main, contiguous 4 items/thread, scan-free ----------------
__global__ void __launch_bounds__(256) k_main(const float* __restrict__ theta,
                                              const void* __restrict__ qidx,
                                              const void* __restrict__ pidx,
                                              const void* __restrict__ seg,
                                              int total, int nq, int bseg) {
    const int is64 = g_is64;
    const int t = blockIdx.x * blockDim.x + threadIdx.x;
    const int i0 = t * 4;
    if (i0 >= total) return;

    int s[4], p[4];
    if (i0 + 4 <= total) {
        if (!is64) {
            const int4* __restrict__ sp4 = (const int4*)((const int*)seg + i0);
            const int4* __restrict__ pp4 = (const int4*)((const int*)pidx + i0);
            int4 sv = *sp4;
            int4 pv = *pp4;
            s[0] = sv.x; s[1] = sv.y; s[2] = sv.z; s[3] = sv.w;
            p[0] = pv.x; p[1] = pv.y; p[2] = pv.z; p[3] = pv.w;
        } else {
            const longlong2* __restrict__ sp2 = (const longlong2*)((const long long*)seg + i0);
            const longlong2* __restrict__ pp2 = (const longlong2*)((const long long*)pidx + i0);
            longlong2 sa = sp2[0];
            longlong2 sb = sp2[1];
            longlong2 pa = pp2[0];
            longlong2 pb = pp2[1];
            s[0] = (int)sa.x; s[1] = (int)sa.y; s[2] = (int)sb.x; s[3] = (int)sb.y;
            p[0] = (int)pa.x; p[1] = (int)pa.y; p[2] = (int)pb.x; p[3] = (int)pb.y;
        }
    } else {
        #pragma unroll
        for (int j = 0; j < 4; j++) {
            int i = i0 + j;
            if (i < total) { s[j] = idx_at(seg, i, is64); p[j] = idx_at(pidx, i, is64); }
            else           { s[j] = -1; p[j] = 0; }
        }
    }

    // theta gathers first (long pole, depends only on pidx)
    float th[4];
    #pragma unroll
    for (int j = 0; j < 4; j++) th[j] = __ldg(&theta[p[j]]);

    // qidx with within-thread segment dedupe (seg sorted -> frequent reuse)
    int q[4];
    q[0] = (s[0] >= 0) ? idx_at(qidx, s[0], is64) : 0;
    #pragma unroll
    for (int j = 1; j < 4; j++)
        q[j] = (s[j] == s[j - 1]) ? q[j - 1]
             : ((s[j] >= 0) ? idx_at(qidx, s[j], is64) : 0);

    // qab gathers with same dedupe
    float2 ab[4];
    ab[0] = g_qab[q[0]];
    #pragma unroll
    for (int j = 1; j < 4; j++)
        ab[j] = (s[j] == s[j - 1]) ? ab[j - 1] : g_qab[q[j]];

    // math
    float v[4];
    #pragma unroll
    for (int j = 0; j < 4; j++) {
        float l = fmaf(ab[j].x, th[j], -ab[j].y);
        l = fminf(fmaxf(l, -20.f), 20.f);
        v[j] = (s[j] >= 0) ? __expf(l) : 0.f;
    }

    // thread-serial run accumulation; flush partials via fused vector red
    float acc = v[0], cnt = (s[0] >= 0) ? 1.f : 0.f;
    #pragma unroll
    for (int j = 1; j < 4; j++) {
        if (s[j] == s[j - 1]) {
            acc += v[j]; cnt += 1.f;
        } else {
            if (s[j - 1] >= 0)
                asm volatile("red.global.add.v2.f32 [%0], {%1, %2};"
                             :: "l"(&g_acc[s[j - 1]]), "f"(acc), "f"(cnt) : "memory");
            acc = v[j]; cnt = (s[j] >= 0) ? 1.f : 0.f;
        }
    }
    if (s[3] >= 0)
        asm volatile("red.global.add.v2.f32 [%0], {%1, %2};"
                     :: "l"(&g_acc[s[3]]), "f"(acc), "f"(cnt) : "memory");
}

// ---------------- kernel 4: finalize (2 segments / thread, float4 loads) ----------------
__global__ void __launch_bounds__(256) k_final(float* __restrict__ out, int n) {
    int i = blockIdx.x * blockDim.x + threadIdx.x;
    int j = 2 * i;
    if (j >= n) return;
    float4 a = *(const float4*)&g_acc[j];

    int ts0 = (int)a.y; ts0 = (ts0 > MAX_TS) ? MAX_TS : ts0; if (ts0 < 0) ts0 = 0;
    float lam0 = a.x * __ldg(&g_exp_ts[ts0]);
    float p0 = fminf(fmaxf(1.f - __expf(-lam0), EPS), 1.f - EPS);

    if (j + 1 < n) {
        int ts1 = (int)a.w; ts1 = (ts1 > MAX_TS) ? MAX_TS : ts1; if (ts1 < 0) ts1 = 0;
        float lam1 = a.z * __ldg(&g_exp_ts[ts1]);
        float p1 = fminf(fmaxf(1.f - __expf(-lam1), EPS), 1.f - EPS);
        *(float2*)&out[j] = make_float2(p0, p1);
    } else {
        out[j] = p0;
    }
}

// ---------------- launch ----------------
extern "C" void kernel_launch(void* const* d_in, const int* in_sizes, int n_in,
                              void* d_out, int out_size) {
    const float* theta     = (const float*)d_in[0];
    const float* b         = (const float*)d_in[1];
    const float* log_a     = (const float*)d_in[2];
    const float* ts_bias   = (const float*)d_in[3];
    const float* dl_scale  = (const float*)d_in[4];
    const float* type_bias = (const float*)d_in[5];
    const float* dl        = (const float*)d_in[6];
    const void*  ttype     = (const void*)d_in[7];
    const void*  qidx      = (const void*)d_in[8];
    const void*  pidx      = (const void*)d_in[9];
    const void*  seg       = (const void*)d_in[10];
    float*       out       = (float*)d_out;

    int nq    = in_sizes[6];
    int bseg  = out_size;
    int total = in_sizes[9];
    if (nq > NQ_MAX) nq = NQ_MAX;
    if (bseg > BSEG_MAX) bseg = BSEG_MAX;

    k_detect<<<1, 32>>>(pidx, ts_bias);
    k_stats<<<512, 256>>>(dl, ttype, nq);

    // k_question also zeroes g_acc: needs max(nq, ceil(bseg/2)) threads
    int qz = nq > (bseg + 1) / 2 ? nq : (bseg + 1) / 2;
    k_question<<<(qz + 255) / 256, 256>>>(b, log_a, dl, ttype, dl_scale, type_bias,
                                          nq, bseg);

    int nthreads = (total + 3) / 4;
    k_main<<<(nthreads + 255) / 256, 256>>>(theta, qidx, pidx, seg, total, nq, bseg);

    k_final<<<(bseg / 2 + 255) / 256, 256>>>(out, bseg);
}

// round 12
// speedup vs baseline: 1.0592x; 1.0592x over previous
#include <cuda_runtime.h>
#include <cuda_bf16.h>
#include <cstdint>

#define NUM_TYPES 3
#define NQ_MAX 500000
#define BSEG_MAX 4000000
#define MAX_TS 10
#define EPS 1e-7f

// ---------------- device scratch (no allocations allowed) ----------------
__device__ float  g_stats[NUM_TYPES * 3];     // per type: sum, sumsq, cnt
__device__ float2 g_qab[NQ_MAX];              // per question: (A=a_i, B=b_i)
__device__ float2 g_acc[BSEG_MAX];            // per segment: (sum exp(logit), count)
__device__ float  g_exp_ts[MAX_TS + 1];       // exp(team_size_bias)
__device__ int    g_is64;                     // 1 if index arrays are int64

__device__ __forceinline__ int idx_at(const void* p, int i, int is64) {
    return is64 ? (int)((const long long*)p)[i] : ((const int*)p)[i];
}

__device__ __forceinline__ void red2(float2* addr, float a, float b) {
    asm volatile("red.global.add.v2.f32 [%0], {%1, %2};"
                 :: "l"(addr), "f"(a), "f"(b) : "memory");
}

// ---------------- kernel 0: detect dtype + zero stats + exp(ts_bias) ----------------
__global__ void k_detect(const void* __restrict__ pidx,
                         const float* __restrict__ ts_bias) {
    if (threadIdx.x < NUM_TYPES * 3) g_stats[threadIdx.x] = 0.f;
    if (threadIdx.x < MAX_TS + 1) g_exp_ts[threadIdx.x] = __expf(ts_bias[threadIdx.x]);
    if (threadIdx.x == 0) {
        const int* p32 = (const int*)pidx;
        int any = 0;
        #pragma unroll 8
        for (int k = 0; k < 256; k++) any |= p32[2 * k + 1];
        g_is64 = (any == 0) ? 1 : 0;
    }
}

// ---------------- kernel 1: per-type dl stats ----------------
__global__ void __launch_bounds__(256) k_stats(const float* __restrict__ dl,
                                               const void* __restrict__ type,
                                               int n) {
    const int is64 = g_is64;
    float s[NUM_TYPES]  = {0.f, 0.f, 0.f};
    float s2[NUM_TYPES] = {0.f, 0.f, 0.f};
    float c[NUM_TYPES]  = {0.f, 0.f, 0.f};
    for (int i = blockIdx.x * blockDim.x + threadIdx.x; i < n;
         i += gridDim.x * blockDim.x) {
        int t = idx_at(type, i, is64);
        if (t < 0) t = 0; if (t >= NUM_TYPES) t = NUM_TYPES - 1;
        float v = dl[i];
        s[t]  += v;
        s2[t] += v * v;
        c[t]  += 1.f;
    }
    const unsigned FULL = 0xffffffffu;
    #pragma unroll
    for (int t = 0; t < NUM_TYPES; t++) {
        #pragma unroll
        for (int d = 16; d > 0; d >>= 1) {
            s[t]  += __shfl_down_sync(FULL, s[t], d);
            s2[t] += __shfl_down_sync(FULL, s2[t], d);
            c[t]  += __shfl_down_sync(FULL, c[t], d);
        }
    }
    __shared__ float sh[NUM_TYPES * 3];
    if (threadIdx.x < NUM_TYPES * 3) sh[threadIdx.x] = 0.f;
    __syncthreads();
    if ((threadIdx.x & 31) == 0) {
        #pragma unroll
        for (int t = 0; t < NUM_TYPES; t++) {
            atomicAdd(&sh[t * 3 + 0], s[t]);
            atomicAdd(&sh[t * 3 + 1], s2[t]);
            atomicAdd(&sh[t * 3 + 2], c[t]);
        }
    }
    __syncthreads();
    if (threadIdx.x < NUM_TYPES * 3) atomicAdd(&g_stats[threadIdx.x], sh[threadIdx.x]);
}

// ---------------- kernel 2: per-question A/B precompute + zero g_acc ----------------
__global__ void __launch_bounds__(256) k_question(const float* __restrict__ b,
                                                  const float* __restrict__ log_a,
                                                  const float* __restrict__ dl,
                                                  const void* __restrict__ type,
                                                  const float* __restrict__ dl_scale,
                                                  const float* __restrict__ type_bias,
                                                  int n, int bseg) {
    int i = blockIdx.x * blockDim.x + threadIdx.x;

    // zero 2 float2 accumulator slots (float4 store)
    int j = i * 2;
    if (j + 1 < bseg) {
        *(float4*)&g_acc[j] = make_float4(0.f, 0.f, 0.f, 0.f);
    } else if (j < bseg) {
        g_acc[j] = make_float2(0.f, 0.f);
    }

    if (i >= n) return;
    int t = idx_at(type, i, g_is64);
    if (t < 0) t = 0; if (t >= NUM_TYPES) t = NUM_TYPES - 1;
    float sum  = g_stats[t * 3 + 0];
    float sum2 = g_stats[t * 3 + 1];
    float cnt  = g_stats[t * 3 + 2];
    float sc   = fmaxf(cnt, 1.f);
    float mean = sum / sc;
    float ex2  = sum2 / sc;
    float stdv = sqrtf(fmaxf(ex2 - mean * mean, 0.f));
    mean = (cnt > 0.f) ? mean : 0.f;
    stdv = (cnt > 0.f && stdv > 1e-6f) ? stdv : 1.f;
    float dln = (dl[i] - mean) / stdv;
    float Bv  = b[i] + type_bias[t] + dl_scale[t] * dln;
    float Av  = fmaxf(expf(log_a[i]), EPS);
    g_qab[i]  = make_float2(Av, Bv);
}

// ---------------- kernel 3: contiguous 4/thread + warp chain-stitch scan ----------------
__global__ void __launch_bounds__(256) k_main(const float* __restrict__ theta,
                                              const void* __restrict__ qidx,
                                              const void* __restrict__ pidx,
                                              const void* __restrict__ seg,
                                              int total, int nq, int bseg) {
    const unsigned FULL = 0xffffffffu;
    const int is64 = g_is64;
    const int lane = threadIdx.x & 31;
    const int t = blockIdx.x * blockDim.x + threadIdx.x;
    const int i0 = t * 4;

    int s[4], p[4];
    if (i0 + 4 <= total) {
        if (!is64) {
            int4 sv = *(const int4*)((const int*)seg + i0);
            int4 pv = *(const int4*)((const int*)pidx + i0);
            s[0] = sv.x; s[1] = sv.y; s[2] = sv.z; s[3] = sv.w;
            p[0] = pv.x; p[1] = pv.y; p[2] = pv.z; p[3] = pv.w;
        } else {
            const longlong2* sp2 = (const longlong2*)((const long long*)seg + i0);
            const longlong2* pp2 = (const longlong2*)((const long long*)pidx + i0);
            longlong2 sa = sp2[0], sb = sp2[1];
            longlong2 pa = pp2[0], pb = pp2[1];
            s[0] = (int)sa.x; s[1] = (int)sa.y; s[2] = (int)sb.x; s[3] = (int)sb.y;
            p[0] = (int)pa.x; p[1] = (int)pa.y; p[2] = (int)pb.x; p[3] = (int)pb.y;
        }
    } else {
        #pragma unroll
        for (int j = 0; j < 4; j++) {
            int i = i0 + j;
            if (i < total) { s[j] = idx_at(seg, i, is64); p[j] = idx_at(pidx, i, is64); }
            else           { s[j] = -1; p[j] = 0; }
        }
    }

    // theta gathers first (long pole, depends only on pidx)
    float th[4];
    #pragma unroll
    for (int j = 0; j < 4; j++) th[j] = __ldg(&theta[p[j]]);

    // qidx with within-thread segment dedupe
    int q[4];
    q[0] = (s[0] >= 0) ? idx_at(qidx, s[0], is64) : 0;
    #pragma unroll
    for (int j = 1; j < 4; j++)
        q[j] = (s[j] == s[j - 1]) ? q[j - 1]
             : ((s[j] >= 0) ? idx_at(qidx, s[j], is64) : 0);

    // qab gathers with same dedupe
    float2 ab[4];
    ab[0] = g_qab[q[0]];
    #pragma unroll
    for (int j = 1; j < 4; j++)
        ab[j] = (s[j] == s[j - 1]) ? ab[j - 1] : g_qab[q[j]];

    // math
    float v[4];
    #pragma unroll
    for (int j = 0; j < 4; j++) {
        float l = fmaf(ab[j].x, th[j], -ab[j].y);
        l = fminf(fmaxf(l, -20.f), 20.f);
        v[j] = (s[j] >= 0) ? __expf(l) : 0.f;
    }

    // serial local reduction: flush interior runs, keep head + tail partials
    float acc = v[0], cnt = (s[0] >= 0) ? 1.f : 0.f;
    float hsum = 0.f, hcnt = 0.f;
    bool from_start = true;
    #pragma unroll
    for (int j = 1; j < 4; j++) {
        if (s[j] == s[j - 1]) {
            acc += v[j]; cnt += (s[j] >= 0) ? 1.f : 0.f;
        } else {
            if (from_start) { hsum = acc; hcnt = cnt; from_start = false; }
            else if (s[j - 1] >= 0) red2(&g_acc[s[j - 1]], acc, cnt);
            acc = v[j]; cnt = (s[j] >= 0) ? 1.f : 0.f;
        }
    }
    const int hseg = s[0];
    const int tseg = s[3];
    const bool transparent = from_start;   // whole thread one segment
    // tail partial = (acc, cnt) for tseg

    // warp segmented scan over tail partials along transparent chains
    int tprev = __shfl_up_sync(FULL, tseg, 1);
    bool fl = (lane == 0) || (!transparent) || (tprev != tseg);
    unsigned bmask = __ballot_sync(FULL, fl);
    unsigned lemask = FULL >> (31 - lane);
    int headlane = 31 - __clz(bmask & lemask);
    float Cs = acc, Cc = cnt;
    #pragma unroll
    for (int d = 1; d < 32; d <<= 1) {
        float us = __shfl_up_sync(FULL, Cs, d);
        float uc = __shfl_up_sync(FULL, Cc, d);
        if (lane - d >= headlane) { Cs += us; Cc += uc; }
    }

    // carry from previous lane for head flush
    float Cps = __shfl_up_sync(FULL, Cs, 1);
    float Cpc = __shfl_up_sync(FULL, Cc, 1);
    if (!transparent && hseg >= 0) {
        float Hs = hsum, Hc = hcnt;
        if (lane > 0 && tprev == hseg) { Hs += Cps; Hc += Cpc; }
        red2(&g_acc[hseg], Hs, Hc);
    }

    // chain-end lanes flush the scanned tail
    int hnext = __shfl_down_sync(FULL, hseg, 1);
    bool chain_end = (lane == 31) || (hnext != tseg);
    if (chain_end && tseg >= 0) red2(&g_acc[tseg], Cs, Cc);
}

// ---------------- kernel 4: finalize (2 segments / thread, float4 loads) ----------------
__global__ void __launch_bounds__(256) k_final(float* __restrict__ out, int n) {
    int i = blockIdx.x * blockDim.x + threadIdx.x;
    int j = 2 * i;
    if (j >= n) return;
    float4 a = *(const float4*)&g_acc[j];

    int ts0 = (int)a.y; ts0 = (ts0 > MAX_TS) ? MAX_TS : ts0; if (ts0 < 0) ts0 = 0;
    float lam0 = a.x * __ldg(&g_exp_ts[ts0]);
    float p0 = fminf(fmaxf(1.f - __expf(-lam0), EPS), 1.f - EPS);

    if (j + 1 < n) {
        int ts1 = (int)a.w; ts1 = (ts1 > MAX_TS) ? MAX_TS : ts1; if (ts1 < 0) ts1 = 0;
        float lam1 = a.z * __ldg(&g_exp_ts[ts1]);
        float p1 = fminf(fmaxf(1.f - __expf(-lam1), EPS), 1.f - EPS);
        *(float2*)&out[j] = make_float2(p0, p1);
    } else {
        out[j] = p0;
    }
}

// ---------------- launch ----------------
extern "C" void kernel_launch(void* const* d_in, const int* in_sizes, int n_in,
                              void* d_out, int out_size) {
    const float* theta     = (const float*)d_in[0];
    const float* b         = (const float*)d_in[1];
    const float* log_a     = (const float*)d_in[2];
    const float* ts_bias   = (const float*)d_in[3];
    const float* dl_scale  = (const float*)d_in[4];
    const float* type_bias = (const float*)d_in[5];
    const float* dl        = (const float*)d_in[6];
    const void*  ttype     = (const void*)d_in[7];
    const void*  qidx      = (const void*)d_in[8];
    const void*  pidx      = (const void*)d_in[9];
    const void*  seg       = (const void*)d_in[10];
    float*       out       = (float*)d_out;

    int nq    = in_sizes[6];
    int bseg  = out_size;
    int total = in_sizes[9];
    if (nq > NQ_MAX) nq = NQ_MAX;
    if (bseg > BSEG_MAX) bseg = BSEG_MAX;

    k_detect<<<1, 32>>>(pidx, ts_bias);
    k_stats<<<512, 256>>>(dl, ttype, nq);

    // k_question also zeroes g_acc: needs max(nq, ceil(bseg/2)) threads
    int qz = nq > (bseg + 1) / 2 ? nq : (bseg + 1) / 2;
    k_question<<<(qz + 255) / 256, 256>>>(b, log_a, dl, ttype, dl_scale, type_bias,
                                          nq, bseg);

    int nthreads = (total + 3) / 4;
    k_main<<<(nthreads + 255) / 256, 256>>>(theta, qidx, pidx, seg, total, nq, bseg);

    k_final<<<(bseg / 2 + 255) / 256, 256>>>(out, bseg);
}

// round 14
// speedup vs baseline: 1.1054x; 1.0437x over previous
#include <cuda_runtime.h>
#include <cuda_bf16.h>
#include <cstdint>

#define NUM_TYPES 3
#define NQ_MAX 500000
#define BSEG_MAX 4000000
#define MAX_TS 10
#define EPS 1e-7f

// ---------------- device scratch (no allocations allowed) ----------------
// g_stats relies on: (a) static zero-init for the very first call, (b) k_final
// re-zeroing it at the end of every call. Every call does identical work.
__device__ float  g_stats[NUM_TYPES * 3];     // per type: sum, sumsq, cnt
__device__ float2 g_qab[NQ_MAX];              // per question: (A=a_i, B=b_i)
__device__ float2 g_acc[BSEG_MAX];            // per segment: (sum, count); zeroed by k_final
__device__ float  g_exp_ts[MAX_TS + 1];       // exp(team_size_bias), written by k_stats

__device__ __forceinline__ int idx_at(const void* p, int i, int is64) {
    return is64 ? (int)((const long long*)p)[i] : ((const int*)p)[i];
}

__device__ __forceinline__ void red2(float2* addr, float a, float b) {
    asm volatile("red.global.add.v2.f32 [%0], {%1, %2};"
                 :: "l"(addr), "f"(a), "f"(b) : "memory");
}

// per-warp index-dtype detect: pidx values < 2^20, so if stored int64 (LE) the
// odd 32-bit words are all zero; 32 random int32 values in [0,1M) are ~never all 0.
__device__ __forceinline__ int warp_detect_is64(const void* pidx) {
    int lane = threadIdx.x & 31;
    int w = ((const int*)pidx)[2 * lane + 1];
    unsigned nz = __ballot_sync(0xffffffffu, w != 0);
    return nz == 0u;
}

// ---------------- kernel 1: per-type dl stats + exp_ts ----------------
__global__ void __launch_bounds__(256) k_stats(const float* __restrict__ dl,
                                               const void* __restrict__ type,
                                               const void* __restrict__ pidx,
                                               const float* __restrict__ ts_bias,
                                               int n) {
    if (blockIdx.x == 0 && threadIdx.x < MAX_TS + 1)
        g_exp_ts[threadIdx.x] = __expf(ts_bias[threadIdx.x]);

    const int is64 = warp_detect_is64(pidx);
    float s[NUM_TYPES]  = {0.f, 0.f, 0.f};
    float s2[NUM_TYPES] = {0.f, 0.f, 0.f};
    float c[NUM_TYPES]  = {0.f, 0.f, 0.f};
    for (int i = blockIdx.x * blockDim.x + threadIdx.x; i < n;
         i += gridDim.x * blockDim.x) {
        int t = idx_at(type, i, is64);
        if (t < 0) t = 0; if (t >= NUM_TYPES) t = NUM_TYPES - 1;
        float v = dl[i];
        s[t]  += v;
        s2[t] += v * v;
        c[t]  += 1.f;
    }
    const unsigned FULL = 0xffffffffu;
    #pragma unroll
    for (int t = 0; t < NUM_TYPES; t++) {
        #pragma unroll
        for (int d = 16; d > 0; d >>= 1) {
            s[t]  += __shfl_down_sync(FULL, s[t], d);
            s2[t] += __shfl_down_sync(FULL, s2[t], d);
            c[t]  += __shfl_down_sync(FULL, c[t], d);
        }
    }
    __shared__ float sh[NUM_TYPES * 3];
    if (threadIdx.x < NUM_TYPES * 3) sh[threadIdx.x] = 0.f;
    __syncthreads();
    if ((threadIdx.x & 31) == 0) {
        #pragma unroll
        for (int t = 0; t < NUM_TYPES; t++) {
            atomicAdd(&sh[t * 3 + 0], s[t]);
            atomicAdd(&sh[t * 3 + 1], s2[t]);
            atomicAdd(&sh[t * 3 + 2], c[t]);
        }
    }
    __syncthreads();
    if (threadIdx.x < NUM_TYPES * 3) atomicAdd(&g_stats[threadIdx.x], sh[threadIdx.x]);
}

// ---------------- kernel 2: per-question A/B precompute ----------------
__global__ void __launch_bounds__(256) k_question(const float* __restrict__ b,
                                                  const float* __restrict__ log_a,
                                                  const float* __restrict__ dl,
                                                  const void* __restrict__ type,
                                                  const void* __restrict__ pidx,
                                                  const float* __restrict__ dl_scale,
                                                  const float* __restrict__ type_bias,
                                                  int n) {
    const int is64 = warp_detect_is64(pidx);
    int i = blockIdx.x * blockDim.x + threadIdx.x;
    if (i >= n) return;
    int t = idx_at(type, i, is64);
    if (t < 0) t = 0; if (t >= NUM_TYPES) t = NUM_TYPES - 1;
    float sum  = g_stats[t * 3 + 0];
    float sum2 = g_stats[t * 3 + 1];
    float cnt  = g_stats[t * 3 + 2];
    float sc   = fmaxf(cnt, 1.f);
    float mean = sum / sc;
    float ex2  = sum2 / sc;
    float stdv = sqrtf(fmaxf(ex2 - mean * mean, 0.f));
    mean = (cnt > 0.f) ? mean : 0.f;
    stdv = (cnt > 0.f && stdv > 1e-6f) ? stdv : 1.f;
    float dln = (dl[i] - mean) / stdv;
    float Bv  = b[i] + type_bias[t] + dl_scale[t] * dln;
    float Av  = fmaxf(expf(log_a[i]), EPS);
    g_qab[i]  = make_float2(Av, Bv);
}

// ---------------- kernel 3: contiguous 4/thread + warp chain-stitch scan ----------------
__global__ void __launch_bounds__(256) k_main(const float* __restrict__ theta,
                                              const void* __restrict__ qidx,
                                              const void* __restrict__ pidx,
                                              const void* __restrict__ seg,
                                              int total, int nq, int bseg) {
    const unsigned FULL = 0xffffffffu;
    const int is64 = warp_detect_is64(pidx);
    const int lane = threadIdx.x & 31;
    const int t = blockIdx.x * blockDim.x + threadIdx.x;
    const int i0 = t * 4;

    int s[4], p[4];
    if (i0 + 4 <= total) {
        if (!is64) {
            int4 sv = *(const int4*)((const int*)seg + i0);
            int4 pv = *(const int4*)((const int*)pidx + i0);
            s[0] = sv.x; s[1] = sv.y; s[2] = sv.z; s[3] = sv.w;
            p[0] = pv.x; p[1] = pv.y; p[2] = pv.z; p[3] = pv.w;
        } else {
            const longlong2* sp2 = (const longlong2*)((const long long*)seg + i0);
            const longlong2* pp2 = (const longlong2*)((const long long*)pidx + i0);
            longlong2 sa = sp2[0], sb = sp2[1];
            longlong2 pa = pp2[0], pb = pp2[1];
            s[0] = (int)sa.x; s[1] = (int)sa.y; s[2] = (int)sb.x; s[3] = (int)sb.y;
            p[0] = (int)pa.x; p[1] = (int)pa.y; p[2] = (int)pb.x; p[3] = (int)pb.y;
        }
    } else {
        #pragma unroll
        for (int j = 0; j < 4; j++) {
            int i = i0 + j;
            if (i < total) { s[j] = idx_at(seg, i, is64); p[j] = idx_at(pidx, i, is64); }
            else           { s[j] = -1; p[j] = 0; }
        }
    }

    // theta gathers first (long pole, depends only on pidx)
    float th[4];
    #pragma unroll
    for (int j = 0; j < 4; j++) th[j] = __ldg(&theta[p[j]]);

    // qidx with within-thread segment dedupe
    int q[4];
    q[0] = (s[0] >= 0) ? idx_at(qidx, s[0], is64) : 0;
    #pragma unroll
    for (int j = 1; j < 4; j++)
        q[j] = (s[j] == s[j - 1]) ? q[j - 1]
             : ((s[j] >= 0) ? idx_at(qidx, s[j], is64) : 0);

    // qab gathers with same dedupe
    float2 ab[4];
    ab[0] = g_qab[q[0]];
    #pragma unroll
    for (int j = 1; j < 4; j++)
        ab[j] = (s[j] == s[j - 1]) ? ab[j - 1] : g_qab[q[j]];

    // math
    float v[4];
    #pragma unroll
    for (int j = 0; j < 4; j++) {
        float l = fmaf(ab[j].x, th[j], -ab[j].y);
        l = fminf(fmaxf(l, -20.f), 20.f);
        v[j] = (s[j] >= 0) ? __expf(l) : 0.f;
    }

    // serial local reduction: flush interior runs, keep head + tail partials
    float acc = v[0], cnt = (s[0] >= 0) ? 1.f : 0.f;
    float hsum = 0.f, hcnt = 0.f;
    bool from_start = true;
    #pragma unroll
    for (int j = 1; j < 4; j++) {
        if (s[j] == s[j - 1]) {
            acc += v[j]; cnt += (s[j] >= 0) ? 1.f : 0.f;
        } else {
            if (from_start) { hsum = acc; hcnt = cnt; from_start = false; }
            else if (s[j - 1] >= 0) red2(&g_acc[s[j - 1]], acc, cnt);
            acc = v[j]; cnt = (s[j] >= 0) ? 1.f : 0.f;
        }
    }
    const int hseg = s[0];
    const int tseg = s[3];
    const bool transparent = from_start;   // whole thread one segment

    // warp segmented scan over tail partials along transparent chains
    int tprev = __shfl_up_sync(FULL, tseg, 1);
    bool fl = (lane == 0) || (!transparent) || (tprev != tseg);
    unsigned bmask = __ballot_sync(FULL, fl);
    unsigned lemask = FULL >> (31 - lane);
    int headlane = 31 - __clz(bmask & lemask);
    float Cs = acc, Cc = cnt;
    #pragma unroll
    for (int d = 1; d < 32; d <<= 1) {
        float us = __shfl_up_sync(FULL, Cs, d);
        float uc = __shfl_up_sync(FULL, Cc, d);
        if (lane - d >= headlane) { Cs += us; Cc += uc; }
    }

    // carry from previous lane for head flush
    float Cps = __shfl_up_sync(FULL, Cs, 1);
    float Cpc = __shfl_up_sync(FULL, Cc, 1);
    if (!transparent && hseg >= 0) {
        float Hs = hsum, Hc = hcnt;
        if (lane > 0 && tprev == hseg) { Hs += Cps; Hc += Cpc; }
        red2(&g_acc[hseg], Hs, Hc);
    }

    // chain-end lanes flush the scanned tail
    int hnext = __shfl_down_sync(FULL, hseg, 1);
    bool chain_end = (lane == 31) || (hnext != tseg);
    if (chain_end && tseg >= 0) red2(&g_acc[tseg], Cs, Cc);
}

// ---------------- kernel 4: finalize 4 segs/thread + restore state ----------------
__global__ void __launch_bounds__(256) k_final(float* __restrict__ out, int n) {
    int i = blockIdx.x * blockDim.x + threadIdx.x;
    int j = 4 * i;

    // restore g_stats for the next call (k_stats accumulates atomically)
    if (i < NUM_TYPES * 3) g_stats[i] = 0.f;

    if (j >= n) return;

    if (j + 4 <= n) {
        float4 a0 = *(const float4*)&g_acc[j];
        float4 a1 = *(const float4*)&g_acc[j + 2];
        float4 r;
        {
            int ts = (int)a0.y; ts = (ts > MAX_TS) ? MAX_TS : ts; if (ts < 0) ts = 0;
            r.x = fminf(fmaxf(1.f - __expf(-a0.x * g_exp_ts[ts]), EPS), 1.f - EPS);
        }
        {
            int ts = (int)a0.w; ts = (ts > MAX_TS) ? MAX_TS : ts; if (ts < 0) ts = 0;
            r.y = fminf(fmaxf(1.f - __expf(-a0.z * g_exp_ts[ts]), EPS), 1.f - EPS);
        }
        {
            int ts = (int)a1.y; ts = (ts > MAX_TS) ? MAX_TS : ts; if (ts < 0) ts = 0;
            r.z = fminf(fmaxf(1.f - __expf(-a1.x * g_exp_ts[ts]), EPS), 1.f - EPS);
        }
        {
            int ts = (int)a1.w; ts = (ts > MAX_TS) ? MAX_TS : ts; if (ts < 0) ts = 0;
            r.w = fminf(fmaxf(1.f - __expf(-a1.z * g_exp_ts[ts]), EPS), 1.f - EPS);
        }
        *(float4*)&out[j] = r;
        // re-zero the accumulator slots for the next call (lines already resident)
        float4 z = make_float4(0.f, 0.f, 0.f, 0.f);
        *(float4*)&g_acc[j]     = z;
        *(float4*)&g_acc[j + 2] = z;
    } else {
        for (int k = j; k < n; k++) {
            float2 a = g_acc[k];
            int ts = (int)a.y; ts = (ts > MAX_TS) ? MAX_TS : ts; if (ts < 0) ts = 0;
            out[k] = fminf(fmaxf(1.f - __expf(-a.x * g_exp_ts[ts]), EPS), 1.f - EPS);
            g_acc[k] = make_float2(0.f, 0.f);
        }
    }
}

// ---------------- launch ----------------
extern "C" void kernel_launch(void* const* d_in, const int* in_sizes, int n_in,
                              void* d_out, int out_size) {
    const float* theta     = (const float*)d_in[0];
    const float* b         = (const float*)d_in[1];
    const float* log_a     = (const float*)d_in[2];
    const float* ts_bias   = (const float*)d_in[3];
    const float* dl_scale  = (const float*)d_in[4];
    const float* type_bias = (const float*)d_in[5];
    const float* dl        = (const float*)d_in[6];
    const void*  ttype     = (const void*)d_in[7];
    const void*  qidx      = (const void*)d_in[8];
    const void*  pidx      = (const void*)d_in[9];
    const void*  seg       = (const void*)d_in[10];
    float*       out       = (float*)d_out;

    int nq    = in_sizes[6];
    int bseg  = out_size;
    int total = in_sizes[9];
    if (nq > NQ_MAX) nq = NQ_MAX;
    if (bseg > BSEG_MAX) bseg = BSEG_MAX;

    k_stats<<<512, 256>>>(dl, ttype, pidx, ts_bias, nq);
    k_question<<<(nq + 255) / 256, 256>>>(b, log_a, dl, ttype, pidx,
                                          dl_scale, type_bias, nq);

    int nthreads = (total + 3) / 4;
    k_main<<<(nthreads + 255) / 256, 256>>>(theta, qidx, pidx, seg, total, nq, bseg);

    k_final<<<((bseg + 3) / 4 + 255) / 256, 256>>>(out, bseg);
}